// round 16
// baseline (speedup 1.0000x reference)
#include <cuda_runtime.h>
#include <cuda_fp16.h>
#include <cstdint>

// Problem constants
#define HEADS 8
#define BATCH 8
#define SEQ   1024          // 32*32
#define HD    64
#define DMODEL 512
#define CIN   512
#define NB    (HEADS*BATCH) // 64 head-batches
#define HSTRIDE (BATCH*SEQ*HD) // 524288 (elements)
#define QSCALE (0.125f * 1.4426950408889634f)   // 1/sqrt(64) * log2(e)
#define MTOT  (BATCH * SEQ)  // 8192

// perm16: within each 16-block, interleave pairs (2c,2c+1),(2c+8,2c+9)
#define PRM16(x) (((((x) >> 1) & 3) << 2) | ((((x) >> 3) & 1) << 1) | ((x) & 1))

// Scratch:
// g_Wt: [z][n][P(k)] fp16 transposed weights (pre-pass)
// g_Q: [n][s][P(hd)] fp16 (pre-scaled by QSCALE); g_K same; g_V: [n][hd][P(s)]
__device__ __half g_Wt[3 * DMODEL * CIN];
__device__ __half g_Q[NB * SEQ * HD];
__device__ __half g_K[NB * SEQ * HD];
__device__ __half g_V[NB * SEQ * HD];

// ---- helpers -------------------------------------------------------------
__device__ __forceinline__ void mma16(float* d, const uint32_t* a, uint32_t b0, uint32_t b1) {
    asm volatile(
        "mma.sync.aligned.m16n8k16.row.col.f32.f16.f16.f32 "
        "{%0,%1,%2,%3}, {%4,%5,%6,%7}, {%8,%9}, {%0,%1,%2,%3};\n"
        : "+f"(d[0]), "+f"(d[1]), "+f"(d[2]), "+f"(d[3])
        : "r"(a[0]), "r"(a[1]), "r"(a[2]), "r"(a[3]), "r"(b0), "r"(b1));
}
__device__ __forceinline__ uint32_t packh(float hi, float lo) {
    uint32_t r; asm("cvt.rn.f16x2.f32 %0, %1, %2;" : "=r"(r) : "f"(hi), "f"(lo)); return r;
}
__device__ __forceinline__ uint32_t ex2h2(uint32_t x) {
    uint32_t r; asm("ex2.approx.f16x2 %0, %1;" : "=r"(r) : "r"(x)); return r;
}
__device__ __forceinline__ void cpa16(uint32_t dst, const void* src) {
    asm volatile("cp.async.ca.shared.global [%0], [%1], 16;\n" :: "r"(dst), "l"(src));
}

// ---------------------------------------------------------------------------
// Pre-pass: W transpose + fp16 perm16 (R15-verified). grid (16,16,3).
// ---------------------------------------------------------------------------
__global__ void __launch_bounds__(256) cvtw_kernel(
    const float* __restrict__ Wq, const float* __restrict__ Wk, const float* __restrict__ Wv)
{
    __shared__ float tile[32][33];
    const int z = blockIdx.z;
    const float* __restrict__ W = (z == 0) ? Wq : (z == 1) ? Wk : Wv;
    const int n0 = blockIdx.x * 32, k0 = blockIdx.y * 32;
    const int tx = threadIdx.x & 31, ty0 = threadIdx.x >> 5;   // (32, 8)
    #pragma unroll
    for (int i = 0; i < 4; i++) {
        const int ty = ty0 + i * 8;
        tile[ty][tx] = W[(size_t)(k0 + ty) * DMODEL + n0 + tx];
    }
    __syncthreads();
    const int pk = k0 + ((tx & ~15) | PRM16(tx & 15));
    #pragma unroll
    for (int i = 0; i < 4; i++) {
        const int ty = ty0 + i * 8;
        g_Wt[(size_t)z * DMODEL * CIN + (size_t)(n0 + ty) * CIN + pk] =
            __float2half_rn(tile[tx][ty]);
    }
}

// ---------------------------------------------------------------------------
// Kernel A: fused Q/K/V projection GEMM, fp16 MMA m16n8k16.
// Hybrid staging: A = R14 path (LDG.128 fp32 + cvt/perm in regs, single smem
// buffer, reg double-buffering). B = g_Wt via cp.async double buffer (no
// scalar gather, no cvt). Warp tile 64x64, 2 CTAs/SM. grid = (4, 64, 3).
// ---------------------------------------------------------------------------
#define AST 48
__global__ void __launch_bounds__(128, 2) proj_kernel(
    const float* __restrict__ Xq, const float* __restrict__ Xk, const float* __restrict__ Xv,
    const float* __restrict__ bq, const float* __restrict__ bk, const float* __restrict__ bv)
{
    __shared__ __half As[128 * AST];        // 12288 B
    __shared__ __half Bs[2][128 * AST];     // 24576 B

    const int z = blockIdx.z;
    const float* __restrict__ X    = (z == 0) ? Xq : (z == 1) ? Xk : Xv;
    const float* __restrict__ bias = (z == 0) ? bq : (z == 1) ? bk : bv;
    __half* __restrict__ Out       = (z == 0) ? g_Q : (z == 1) ? g_K : g_V;

    const int m0 = blockIdx.y * 128;
    const int n0 = blockIdx.x * 128;
    const int tid = threadIdx.x;
    const int lane = tid & 31, warp = tid >> 5;
    const int wm = (warp & 1) * 64;
    const int wn = (warp >> 1) * 64;

    const float* asrc0 = X + (size_t)(m0 + tid) * CIN;       // thread = A row
    const __half* bsrc0 = g_Wt + (size_t)z * DMODEL * CIN + (size_t)(n0 + tid) * CIN;
    __half* adst = As + tid * AST;
    const uint32_t bs_a = (uint32_t)__cvta_generic_to_shared(&Bs[0][0]);

    #define B_ISSUE(t, buf) do {                                              \
        uint32_t bd = bs_a + (uint32_t)(((buf) * 128 * AST + tid * AST) * 2); \
        const __half* bx = bsrc0 + (t) * 32;                                  \
        cpa16(bd, bx); cpa16(bd + 16, bx + 8);                                \
        cpa16(bd + 32, bx + 16); cpa16(bd + 48, bx + 24);                     \
        asm volatile("cp.async.commit_group;\n" ::: "memory");                \
    } while (0)

    float4 ra[8];
    #pragma unroll
    for (int j = 0; j < 8; j++) ra[j] = *(const float4*)(asrc0 + 4 * j);

    B_ISSUE(0, 0);

    float c[4][8][4];
    #pragma unroll
    for (int mt = 0; mt < 4; mt++)
        #pragma unroll
        for (int nt = 0; nt < 8; nt++)
            #pragma unroll
            for (int i = 0; i < 4; i++) c[mt][nt][i] = 0.0f;

    for (int t = 0; t < 16; t++) {
        __syncthreads();   // previous compute done before overwriting A smem
        {
            // fp16 convert + perm16 repack of A (register work), 4 STS.128
            __half ha[32];
            const float* rf = (const float*)ra;
            #pragma unroll
            for (int k = 0; k < 32; k++)
                ha[(k & ~15) | PRM16(k & 15)] = __float2half_rn(rf[k]);
            #pragma unroll
            for (int j = 0; j < 4; j++)
                *(uint4*)(adst + 8 * j) = *(const uint4*)(ha + 8 * j);
        }
        if (t + 1 < 16) {
            B_ISSUE(t + 1, (t + 1) & 1);
            asm volatile("cp.async.wait_group 1;\n" ::: "memory");   // B(t) ready
        } else {
            asm volatile("cp.async.wait_group 0;\n" ::: "memory");
        }
        __syncthreads();

        if (t + 1 < 16) {  // prefetch next A chunk; LDG latency overlaps compute
            const float* an = asrc0 + (t + 1) * 32;
            #pragma unroll
            for (int j = 0; j < 8; j++) ra[j] = *(const float4*)(an + 4 * j);
        }

        const __half* Bf = &Bs[t & 1][0];
        #pragma unroll
        for (int ks = 0; ks < 2; ks++) {
            uint32_t A[4][4];
            #pragma unroll
            for (int mt = 0; mt < 4; mt++) {
                const __half* ap = As + (wm + mt * 16 + (lane >> 2)) * AST + 16 * ks + 4 * (lane & 3);
                uint2 lo = *(const uint2*)ap;
                uint2 hi = *(const uint2*)(ap + 8 * AST);
                A[mt][0] = lo.x; A[mt][1] = hi.x;
                A[mt][2] = lo.y; A[mt][3] = hi.y;
            }
            #pragma unroll
            for (int nt = 0; nt < 8; nt++) {
                const __half* bp = Bf + (wn + 8 * nt + (lane >> 2)) * AST + 16 * ks + 4 * (lane & 3);
                uint2 bb = *(const uint2*)bp;
                #pragma unroll
                for (int mt = 0; mt < 4; mt++) mma16(c[mt][nt], A[mt], bb.x, bb.y);
            }
        }
    }
    #undef B_ISSUE

    // Epilogue: bias + fp16 round + perm16 layout scatter (R14-verified)
    #pragma unroll
    for (int mt = 0; mt < 4; mt++) {
        #pragma unroll
        for (int nt = 0; nt < 8; nt++) {
            const int d = n0 + wn + 8 * nt + 2 * (lane & 3);
            const float2 bb = *(const float2*)&bias[d];
            const int head = d >> 6;
            const int dh = d & 63;                       // even
            const int pq = (dh & ~15) | PRM16(dh & 15);  // pair -> (pq, pq+1)
            #pragma unroll
            for (int rh = 0; rh < 2; rh++) {
                const int m = m0 + wm + 16 * mt + (lane >> 2) + 8 * rh;
                float v0 = c[mt][nt][2 * rh] + bb.x;
                float v1 = c[mt][nt][2 * rh + 1] + bb.y;
                if (z == 0) { v0 *= QSCALE; v1 *= QSCALE; }
                const __half h0 = __float2half_rn(v0);
                const __half h1 = __float2half_rn(v1);
                if (z == 2) {
                    const int b = m >> 10, s = m & 1023;
                    const int ps = (s & ~15) | PRM16(s & 15);
                    __half* base = Out + (size_t)head * HSTRIDE + (size_t)b * (SEQ * HD) + ps;
                    base[(size_t)dh * SEQ]       = h0;
                    base[(size_t)(dh + 1) * SEQ] = h1;
                } else {
                    __half* base = Out + (size_t)head * HSTRIDE + (size_t)m * HD + pq;
                    *(__half2*)base = __halves2half2(h0, h1);
                }
            }
        }
    }
}

// ---------------------------------------------------------------------------
// Kernel B: flash attention, fp16 MMA. R13/R14 structure with the softmax
// moved to f16x2: pack raw scores -> ex2.approx.f16x2 (16 MUFU vs 32);
// lrow via HADD2 of the same fp16 p values (consistent with PV numerator).
// ---------------------------------------------------------------------------
#define KSTRh 80
#define VSTRh 48

__global__ void __launch_bounds__(128, 2) attn_kernel(float* __restrict__ out)
{
    __shared__ __half Ks[2][32 * KSTRh];   // 10240 B
    __shared__ __half Vs[2][64 * VSTRh];   // 12288 B

    const int n = blockIdx.y;
    const int tid = threadIdx.x;
    const int lane = tid & 31, warp = tid >> 5;
    const int q0 = blockIdx.x * 128;

    const __half* Kg = g_K + (size_t)n * SEQ * HD;
    const __half* Vg = g_V + (size_t)n * SEQ * HD;   // [64][1024]

    uint32_t qA[2][4][4];
    {
        #pragma unroll
        for (int mt = 0; mt < 2; mt++) {
            const int row = q0 + warp * 32 + mt * 16 + (lane >> 2);
            const __half* rp = g_Q + ((size_t)n * SEQ + row) * HD;
            #pragma unroll
            for (int ks = 0; ks < 4; ks++) {
                uint2 lo = *(const uint2*)(rp + 16 * ks + 4 * (lane & 3));
                uint2 hi = *(const uint2*)(rp + 8 * HD + 16 * ks + 4 * (lane & 3));
                qA[mt][ks][0] = lo.x; qA[mt][ks][1] = hi.x;
                qA[mt][ks][2] = lo.y; qA[mt][ks][3] = hi.y;
            }
        }
    }

    float o[2][8][4];
    #pragma unroll
    for (int mt = 0; mt < 2; mt++)
        #pragma unroll
        for (int nt = 0; nt < 8; nt++)
            #pragma unroll
            for (int i = 0; i < 4; i++) o[mt][nt][i] = 0.0f;
    float lrow[4] = {0.0f, 0.0f, 0.0f, 0.0f};

    const int krow = tid >> 2, kc = tid & 3;
    const int vrow = tid >> 1, vc = tid & 1;
    const uint32_t ks_a = (uint32_t)__cvta_generic_to_shared(&Ks[0][0]);
    const uint32_t vs_a = (uint32_t)__cvta_generic_to_shared(&Vs[0][0]);

    #define ISSUE_TILE(kv, b) do {                                                 \
        uint32_t kd = ks_a + (uint32_t)(((b) * 32 * KSTRh + krow * KSTRh) * 2 + kc * 32); \
        const __half* ksrc = Kg + (size_t)((kv) + krow) * HD + kc * 16;            \
        cpa16(kd, ksrc); cpa16(kd + 16, ksrc + 8);                                 \
        uint32_t vd = vs_a + (uint32_t)(((b) * 64 * VSTRh + vrow * VSTRh) * 2 + vc * 32); \
        const __half* vsrc = Vg + (size_t)vrow * SEQ + (kv) + vc * 16;             \
        cpa16(vd, vsrc); cpa16(vd + 16, vsrc + 8);                                 \
        asm volatile("cp.async.commit_group;\n" ::: "memory");                     \
    } while (0)

    ISSUE_TILE(0, 0);

    for (int t = 0; t < 32; t++) {
        if (t + 1 < 32) {
            ISSUE_TILE((t + 1) * 32, (t + 1) & 1);
            asm volatile("cp.async.wait_group 1;\n" ::: "memory");
        } else {
            asm volatile("cp.async.wait_group 0;\n" ::: "memory");
        }
        __syncthreads();
        const __half* Kb = &Ks[t & 1][0];
        const __half* Vb = &Vs[t & 1][0];

        float s[2][4][4];
        #pragma unroll
        for (int mt = 0; mt < 2; mt++)
            #pragma unroll
            for (int nt = 0; nt < 4; nt++)
                #pragma unroll
                for (int i = 0; i < 4; i++) s[mt][nt][i] = 0.0f;

        #pragma unroll
        for (int ks = 0; ks < 4; ks++) {
            #pragma unroll
            for (int nt = 0; nt < 4; nt++) {
                uint2 kv2 = *(const uint2*)&Kb[(8 * nt + (lane >> 2)) * KSTRh + 16 * ks + 4 * (lane & 3)];
                mma16(s[0][nt], qA[0][ks], kv2.x, kv2.y);
                mma16(s[1][nt], qA[1][ks], kv2.x, kv2.y);
            }
        }

        // ---- P = exp2(S) in f16x2 (half the MUFU ops); lrow via HADD2 ----
        uint32_t pA[2][2][4];
        #pragma unroll
        for (int mt = 0; mt < 2; mt++) {
            #pragma unroll
            for (int kt = 0; kt < 2; kt++) {
                pA[mt][kt][0] = ex2h2(packh(s[mt][2 * kt][1],     s[mt][2 * kt][0]));
                pA[mt][kt][1] = ex2h2(packh(s[mt][2 * kt][3],     s[mt][2 * kt][2]));
                pA[mt][kt][2] = ex2h2(packh(s[mt][2 * kt + 1][1], s[mt][2 * kt + 1][0]));
                pA[mt][kt][3] = ex2h2(packh(s[mt][2 * kt + 1][3], s[mt][2 * kt + 1][2]));
            }
            {   // rows r (slots c0,c1): pA[.][.][0] and [2]
                __half2 t0 = __hadd2(
                    __hadd2(*(__half2*)&pA[mt][0][0], *(__half2*)&pA[mt][0][2]),
                    __hadd2(*(__half2*)&pA[mt][1][0], *(__half2*)&pA[mt][1][2]));
                float2 f0 = __half22float2(t0);
                lrow[mt * 2 + 0] += f0.x + f0.y;
            }
            {   // rows r+8 (slots c2,c3): pA[.][.][1] and [3]
                __half2 t1 = __hadd2(
                    __hadd2(*(__half2*)&pA[mt][0][1], *(__half2*)&pA[mt][0][3]),
                    __hadd2(*(__half2*)&pA[mt][1][1], *(__half2*)&pA[mt][1][3]));
                float2 f1 = __half22float2(t1);
                lrow[mt * 2 + 1] += f1.x + f1.y;
            }
        }

        #pragma unroll
        for (int kt = 0; kt < 2; kt++) {
            #pragma unroll
            for (int nt = 0; nt < 8; nt++) {
                uint2 vv = *(const uint2*)&Vb[(8 * nt + (lane >> 2)) * VSTRh + 16 * kt + 4 * (lane & 3)];
                mma16(o[0][nt], pA[0][kt], vv.x, vv.y);
                mma16(o[1][nt], pA[1][kt], vv.x, vv.y);
            }
        }
        __syncthreads();
    }
    #undef ISSUE_TILE

    const int head = n >> 3, b = n & 7;
    #pragma unroll
    for (int sl = 0; sl < 4; sl++) {
        lrow[sl] += __shfl_xor_sync(0xffffffffu, lrow[sl], 1);
        lrow[sl] += __shfl_xor_sync(0xffffffffu, lrow[sl], 2);
    }
    #pragma unroll
    for (int mt = 0; mt < 2; mt++) {
        #pragma unroll
        for (int rh = 0; rh < 2; rh++) {
            const int q = q0 + warp * 32 + mt * 16 + (lane >> 2) + 8 * rh;
            const float inv = 1.0f / lrow[mt * 2 + rh];
            float* orow = out + ((size_t)(b * SEQ + q)) * DMODEL + head * HD;
            #pragma unroll
            for (int nt = 0; nt < 8; nt++) {
                const int cc = 8 * nt + 2 * (lane & 3);
                *(float2*)(orow + cc) =
                    make_float2(o[mt][nt][2 * rh] * inv, o[mt][nt][2 * rh + 1] * inv);
            }
        }
    }
}

extern "C" void kernel_launch(void* const* d_in, const int* in_sizes, int n_in,
                              void* d_out, int out_size)
{
    const float* q_in = (const float*)d_in[0];
    const float* k_in = (const float*)d_in[1];
    const float* v_in = (const float*)d_in[2];
    const float* Wq   = (const float*)d_in[3];
    const float* bq   = (const float*)d_in[4];
    const float* Wk   = (const float*)d_in[5];
    const float* bk   = (const float*)d_in[6];
    const float* Wv   = (const float*)d_in[7];
    const float* bv   = (const float*)d_in[8];
    float* out = (float*)d_out;

    cvtw_kernel<<<dim3(16, 16, 3), 256>>>(Wq, Wk, Wv);

    dim3 gp(DMODEL / 128, MTOT / 128, 3);            // (4, 64, 3)
    proj_kernel<<<gp, 128>>>(q_in, k_in, v_in, bq, bk, bv);

    dim3 ga(SEQ / 128, NB);                          // (8, 64)
    attn_kernel<<<ga, 128>>>(out);
}

// round 17
// speedup vs baseline: 1.1110x; 1.1110x over previous
#include <cuda_runtime.h>
#include <cuda_fp16.h>
#include <cstdint>

// Problem constants
#define HEADS 8
#define BATCH 8
#define SEQ   1024          // 32*32
#define HD    64
#define DMODEL 512
#define CIN   512
#define NB    (HEADS*BATCH) // 64 head-batches
#define HSTRIDE (BATCH*SEQ*HD) // 524288 (elements)
#define QSCALE (0.125f * 1.4426950408889634f)   // 1/sqrt(64) * log2(e)

// perm16: within each 16-block, interleave pairs (2c,2c+1),(2c+8,2c+9)
#define PRM16(x) (((((x) >> 1) & 3) << 2) | ((((x) >> 3) & 1) << 1) | ((x) & 1))

// Scratch (fp16, written by proj epilogue):
// g_Q: [n][s][P(hd)]  (pre-scaled by QSCALE)
// g_K: [n][s][P(hd)]
// g_V: [n][hd][P(s)]  (transposed per head-batch)
__device__ __half g_Q[NB * SEQ * HD];
__device__ __half g_K[NB * SEQ * HD];
__device__ __half g_V[NB * SEQ * HD];

// ---- helpers -------------------------------------------------------------
__device__ __forceinline__ void mma16(float* d, const uint32_t* a, uint32_t b0, uint32_t b1) {
    asm volatile(
        "mma.sync.aligned.m16n8k16.row.col.f32.f16.f16.f32 "
        "{%0,%1,%2,%3}, {%4,%5,%6,%7}, {%8,%9}, {%0,%1,%2,%3};\n"
        : "+f"(d[0]), "+f"(d[1]), "+f"(d[2]), "+f"(d[3])
        : "r"(a[0]), "r"(a[1]), "r"(a[2]), "r"(a[3]), "r"(b0), "r"(b1));
}
__device__ __forceinline__ uint32_t packh(float hi, float lo) {
    uint32_t r; asm("cvt.rn.f16x2.f32 %0, %1, %2;" : "=r"(r) : "f"(hi), "f"(lo)); return r;
}
__device__ __forceinline__ uint32_t ex2h2(uint32_t x) {
    uint32_t r; asm("ex2.approx.f16x2 %0, %1;" : "=r"(r) : "r"(x)); return r;
}
__device__ __forceinline__ void cpa16(uint32_t dst, const void* src) {
    asm volatile("cp.async.ca.shared.global [%0], [%1], 16;\n" :: "r"(dst), "l"(src));
}

// ---------------------------------------------------------------------------
// Kernel A: fused Q/K/V projection GEMM, fp16 MMA m16n8k16 (R14 — verbatim,
// best measured proj ~100us). Block 128x128 tile, 4 warps, warp tile 64x64,
// 2 CTAs/SM, register double-buffering, cvt+perm in regs at staging.
// ---------------------------------------------------------------------------
#define AST 48
__global__ void __launch_bounds__(128, 2) proj_kernel(
    const float* __restrict__ Xq, const float* __restrict__ Xk, const float* __restrict__ Xv,
    const float* __restrict__ Wq, const float* __restrict__ Wk, const float* __restrict__ Wv,
    const float* __restrict__ bq, const float* __restrict__ bk, const float* __restrict__ bv)
{
    __shared__ __half As[128 * AST];   // 12288 B
    __shared__ __half Bs[128 * AST];   // 12288 B

    const int z = blockIdx.z;
    const float* __restrict__ X    = (z == 0) ? Xq : (z == 1) ? Xk : Xv;
    const float* __restrict__ W    = (z == 0) ? Wq : (z == 1) ? Wk : Wv;
    const float* __restrict__ bias = (z == 0) ? bq : (z == 1) ? bk : bv;
    __half* __restrict__ Out       = (z == 0) ? g_Q : (z == 1) ? g_K : g_V;

    const int m0 = blockIdx.y * 128;
    const int n0 = blockIdx.x * 128;
    const int tid = threadIdx.x;
    const int lane = tid & 31, warp = tid >> 5;
    const int wm = (warp & 1) * 64;
    const int wn = (warp >> 1) * 64;

    const float* asrc0 = X + (size_t)(m0 + tid) * CIN;   // thread = A row
    const float* wsrc0 = W + n0 + tid;                   // thread = W column
    __half* adst = As + tid * AST;
    __half* bdst = Bs + tid * AST;

    float4 ra[8];
    float wr[32];
    #pragma unroll
    for (int j = 0; j < 8; j++) ra[j] = *(const float4*)(asrc0 + 4 * j);
    #pragma unroll
    for (int k = 0; k < 32; k++) wr[k] = wsrc0[(size_t)k * DMODEL];

    float c[4][8][4];
    #pragma unroll
    for (int mt = 0; mt < 4; mt++)
        #pragma unroll
        for (int nt = 0; nt < 8; nt++)
            #pragma unroll
            for (int i = 0; i < 4; i++) c[mt][nt][i] = 0.0f;

    for (int t = 0; t < 16; t++) {
        __syncthreads();   // previous compute done before overwriting smem
        {
            __half ha[32], hb[32];
            const float* rf = (const float*)ra;
            #pragma unroll
            for (int k = 0; k < 32; k++) {
                ha[(k & ~15) | PRM16(k & 15)] = __float2half_rn(rf[k]);
                hb[(k & ~15) | PRM16(k & 15)] = __float2half_rn(wr[k]);
            }
            #pragma unroll
            for (int j = 0; j < 4; j++) {
                *(uint4*)(adst + 8 * j) = *(const uint4*)(ha + 8 * j);
                *(uint4*)(bdst + 8 * j) = *(const uint4*)(hb + 8 * j);
            }
        }
        __syncthreads();

        if (t + 1 < 16) {  // prefetch next chunk; LDG latency overlaps compute
            const float* an = asrc0 + (t + 1) * 32;
            const float* wn_ = wsrc0 + (size_t)(t + 1) * 32 * DMODEL;
            #pragma unroll
            for (int j = 0; j < 8; j++) ra[j] = *(const float4*)(an + 4 * j);
            #pragma unroll
            for (int k = 0; k < 32; k++) wr[k] = wn_[(size_t)k * DMODEL];
        }

        #pragma unroll
        for (int ks = 0; ks < 2; ks++) {
            uint32_t A[4][4];
            #pragma unroll
            for (int mt = 0; mt < 4; mt++) {
                const __half* ap = As + (wm + mt * 16 + (lane >> 2)) * AST + 16 * ks + 4 * (lane & 3);
                uint2 lo = *(const uint2*)ap;
                uint2 hi = *(const uint2*)(ap + 8 * AST);
                A[mt][0] = lo.x; A[mt][1] = hi.x;
                A[mt][2] = lo.y; A[mt][3] = hi.y;
            }
            #pragma unroll
            for (int nt = 0; nt < 8; nt++) {
                const __half* bp = Bs + (wn + 8 * nt + (lane >> 2)) * AST + 16 * ks + 4 * (lane & 3);
                uint2 bb = *(const uint2*)bp;
                #pragma unroll
                for (int mt = 0; mt < 4; mt++) mma16(c[mt][nt], A[mt], bb.x, bb.y);
            }
        }
    }

    // Epilogue: bias + fp16 round + perm16 layout scatter
    #pragma unroll
    for (int mt = 0; mt < 4; mt++) {
        #pragma unroll
        for (int nt = 0; nt < 8; nt++) {
            const int d = n0 + wn + 8 * nt + 2 * (lane & 3);
            const float2 bb = *(const float2*)&bias[d];
            const int head = d >> 6;
            const int dh = d & 63;                       // even
            const int pq = (dh & ~15) | PRM16(dh & 15);  // pair -> (pq, pq+1)
            #pragma unroll
            for (int rh = 0; rh < 2; rh++) {
                const int m = m0 + wm + 16 * mt + (lane >> 2) + 8 * rh;
                float v0 = c[mt][nt][2 * rh] + bb.x;
                float v1 = c[mt][nt][2 * rh + 1] + bb.y;
                if (z == 0) { v0 *= QSCALE; v1 *= QSCALE; }
                const __half h0 = __float2half_rn(v0);
                const __half h1 = __float2half_rn(v1);
                if (z == 2) {
                    const int b = m >> 10, s = m & 1023;
                    const int ps = (s & ~15) | PRM16(s & 15);
                    __half* base = Out + (size_t)head * HSTRIDE + (size_t)b * (SEQ * HD) + ps;
                    base[(size_t)dh * SEQ]       = h0;
                    base[(size_t)(dh + 1) * SEQ] = h1;
                } else {
                    __half* base = Out + (size_t)head * HSTRIDE + (size_t)m * HD + pq;
                    *(__half2*)base = __halves2half2(h0, h1);
                }
            }
        }
    }
}

// ---------------------------------------------------------------------------
// Kernel B: flash attention, fp16 MMA. R14 structure with the softmax moved
// to f16x2: pack raw scores -> ex2.approx.f16x2 (16 MUFU ops vs 32);
// lrow via HADD2 of the same fp16 p values (consistent num/denominator).
// ---------------------------------------------------------------------------
#define KSTRh 80
#define VSTRh 48

__global__ void __launch_bounds__(128, 2) attn_kernel(float* __restrict__ out)
{
    __shared__ __half Ks[2][32 * KSTRh];   // 10240 B
    __shared__ __half Vs[2][64 * VSTRh];   // 12288 B

    const int n = blockIdx.y;
    const int tid = threadIdx.x;
    const int lane = tid & 31, warp = tid >> 5;
    const int q0 = blockIdx.x * 128;

    const __half* Kg = g_K + (size_t)n * SEQ * HD;
    const __half* Vg = g_V + (size_t)n * SEQ * HD;   // [64][1024]

    uint32_t qA[2][4][4];
    {
        #pragma unroll
        for (int mt = 0; mt < 2; mt++) {
            const int row = q0 + warp * 32 + mt * 16 + (lane >> 2);
            const __half* rp = g_Q + ((size_t)n * SEQ + row) * HD;
            #pragma unroll
            for (int ks = 0; ks < 4; ks++) {
                uint2 lo = *(const uint2*)(rp + 16 * ks + 4 * (lane & 3));
                uint2 hi = *(const uint2*)(rp + 8 * HD + 16 * ks + 4 * (lane & 3));
                qA[mt][ks][0] = lo.x; qA[mt][ks][1] = hi.x;
                qA[mt][ks][2] = lo.y; qA[mt][ks][3] = hi.y;
            }
        }
    }

    float o[2][8][4];
    #pragma unroll
    for (int mt = 0; mt < 2; mt++)
        #pragma unroll
        for (int nt = 0; nt < 8; nt++)
            #pragma unroll
            for (int i = 0; i < 4; i++) o[mt][nt][i] = 0.0f;
    float lrow[4] = {0.0f, 0.0f, 0.0f, 0.0f};

    const int krow = tid >> 2, kc = tid & 3;
    const int vrow = tid >> 1, vc = tid & 1;
    const uint32_t ks_a = (uint32_t)__cvta_generic_to_shared(&Ks[0][0]);
    const uint32_t vs_a = (uint32_t)__cvta_generic_to_shared(&Vs[0][0]);

    #define ISSUE_TILE(kv, b) do {                                                 \
        uint32_t kd = ks_a + (uint32_t)(((b) * 32 * KSTRh + krow * KSTRh) * 2 + kc * 32); \
        const __half* ksrc = Kg + (size_t)((kv) + krow) * HD + kc * 16;            \
        cpa16(kd, ksrc); cpa16(kd + 16, ksrc + 8);                                 \
        uint32_t vd = vs_a + (uint32_t)(((b) * 64 * VSTRh + vrow * VSTRh) * 2 + vc * 32); \
        const __half* vsrc = Vg + (size_t)vrow * SEQ + (kv) + vc * 16;             \
        cpa16(vd, vsrc); cpa16(vd + 16, vsrc + 8);                                 \
        asm volatile("cp.async.commit_group;\n" ::: "memory");                     \
    } while (0)

    ISSUE_TILE(0, 0);

    for (int t = 0; t < 32; t++) {
        if (t + 1 < 32) {
            ISSUE_TILE((t + 1) * 32, (t + 1) & 1);
            asm volatile("cp.async.wait_group 1;\n" ::: "memory");
        } else {
            asm volatile("cp.async.wait_group 0;\n" ::: "memory");
        }
        __syncthreads();
        const __half* Kb = &Ks[t & 1][0];
        const __half* Vb = &Vs[t & 1][0];

        float s[2][4][4];
        #pragma unroll
        for (int mt = 0; mt < 2; mt++)
            #pragma unroll
            for (int nt = 0; nt < 4; nt++)
                #pragma unroll
                for (int i = 0; i < 4; i++) s[mt][nt][i] = 0.0f;

        #pragma unroll
        for (int ks = 0; ks < 4; ks++) {
            #pragma unroll
            for (int nt = 0; nt < 4; nt++) {
                uint2 kv2 = *(const uint2*)&Kb[(8 * nt + (lane >> 2)) * KSTRh + 16 * ks + 4 * (lane & 3)];
                mma16(s[0][nt], qA[0][ks], kv2.x, kv2.y);
                mma16(s[1][nt], qA[1][ks], kv2.x, kv2.y);
            }
        }

        // ---- P = exp2(S) in f16x2 (half the MUFU ops); lrow via HADD2 ----
        uint32_t pA[2][2][4];
        #pragma unroll
        for (int mt = 0; mt < 2; mt++) {
            #pragma unroll
            for (int kt = 0; kt < 2; kt++) {
                pA[mt][kt][0] = ex2h2(packh(s[mt][2 * kt][1],     s[mt][2 * kt][0]));
                pA[mt][kt][1] = ex2h2(packh(s[mt][2 * kt][3],     s[mt][2 * kt][2]));
                pA[mt][kt][2] = ex2h2(packh(s[mt][2 * kt + 1][1], s[mt][2 * kt + 1][0]));
                pA[mt][kt][3] = ex2h2(packh(s[mt][2 * kt + 1][3], s[mt][2 * kt + 1][2]));
            }
            {   // rows r (c0,c1): regs [0] and [2]
                __half2 t0 = __hadd2(
                    __hadd2(*(__half2*)&pA[mt][0][0], *(__half2*)&pA[mt][0][2]),
                    __hadd2(*(__half2*)&pA[mt][1][0], *(__half2*)&pA[mt][1][2]));
                float2 f0 = __half22float2(t0);
                lrow[mt * 2 + 0] += f0.x + f0.y;
            }
            {   // rows r+8 (c2,c3): regs [1] and [3]
                __half2 t1 = __hadd2(
                    __hadd2(*(__half2*)&pA[mt][0][1], *(__half2*)&pA[mt][0][3]),
                    __hadd2(*(__half2*)&pA[mt][1][1], *(__half2*)&pA[mt][1][3]));
                float2 f1 = __half22float2(t1);
                lrow[mt * 2 + 1] += f1.x + f1.y;
            }
        }

        #pragma unroll
        for (int kt = 0; kt < 2; kt++) {
            #pragma unroll
            for (int nt = 0; nt < 8; nt++) {
                uint2 vv = *(const uint2*)&Vb[(8 * nt + (lane >> 2)) * VSTRh + 16 * kt + 4 * (lane & 3)];
                mma16(o[0][nt], pA[0][kt], vv.x, vv.y);
                mma16(o[1][nt], pA[1][kt], vv.x, vv.y);
            }
        }
        __syncthreads();
    }
    #undef ISSUE_TILE

    const int head = n >> 3, b = n & 7;
    #pragma unroll
    for (int sl = 0; sl < 4; sl++) {
        lrow[sl] += __shfl_xor_sync(0xffffffffu, lrow[sl], 1);
        lrow[sl] += __shfl_xor_sync(0xffffffffu, lrow[sl], 2);
    }
    #pragma unroll
    for (int mt = 0; mt < 2; mt++) {
        #pragma unroll
        for (int rh = 0; rh < 2; rh++) {
            const int q = q0 + warp * 32 + mt * 16 + (lane >> 2) + 8 * rh;
            const float inv = 1.0f / lrow[mt * 2 + rh];
            float* orow = out + ((size_t)(b * SEQ + q)) * DMODEL + head * HD;
            #pragma unroll
            for (int nt = 0; nt < 8; nt++) {
                const int cc = 8 * nt + 2 * (lane & 3);
                *(float2*)(orow + cc) =
                    make_float2(o[mt][nt][2 * rh] * inv, o[mt][nt][2 * rh + 1] * inv);
            }
        }
    }
}

extern "C" void kernel_launch(void* const* d_in, const int* in_sizes, int n_in,
                              void* d_out, int out_size)
{
    const float* q_in = (const float*)d_in[0];
    const float* k_in = (const float*)d_in[1];
    const float* v_in = (const float*)d_in[2];
    const float* Wq   = (const float*)d_in[3];
    const float* bq   = (const float*)d_in[4];
    const float* Wk   = (const float*)d_in[5];
    const float* bk   = (const float*)d_in[6];
    const float* Wv   = (const float*)d_in[7];
    const float* bv   = (const float*)d_in[8];
    float* out = (float*)d_out;

    dim3 gp(DMODEL / 128, (BATCH * SEQ) / 128, 3);   // (4, 64, 3)
    proj_kernel<<<gp, 128>>>(q_in, k_in, v_in, Wq, Wk, Wv, bq, bk, bv);

    dim3 ga(SEQ / 128, NB);                          // (8, 64)
    attn_kernel<<<ga, 128>>>(out);
}